// round 6
// baseline (speedup 1.0000x reference)
#include <cuda_runtime.h>
#include <cstdint>

// Problem constants
#define BSZ 128
#define SDIM 1024
#define AD 128
#define HH 512
#define OUT_T 513

// Grid/tiling
#define NCTA 128
#define NTHREADS 256
#define CLUSTER 4
#define MT 32
#define NT 32
#define WOCT 36               // per-warp octets: 32 x + 4 u

// SMEM word offsets.
// Chunk A (k 0..511):   words [0, 16384)      = half0 8192 | half1 8192
// Chunk B (k 512..1023):words [16384, 32768)
// U region (k 1024..):  words [32768, 36864)  = half0 2048 | half1 2048
#define CHA 0
#define CHB 16384
#define UREG 32768
#define REDO 36864
#define RED_STRIDE 40
#define RED_W (8 * 16 * RED_STRIDE)   // 5120 words
#define MBAR_W (REDO + RED_W)         // 41984 (byte offset 167936, 8B aligned)
#define SMEM_BYTES ((MBAR_W + 8) * 4)

// Global sync state (zero-init once; epochs monotonic across graph replays)
__device__ unsigned g_arrive[NCTA];
__device__ unsigned g_release;
__device__ unsigned g_flag[4][32];

// tf32 state double buffer; per-mt block of 32768 words laid out EXACTLY like
// smem chunks A|B so staging is 4 contiguous 32KB bulk copies.
__device__ __align__(16) uint32_t g_xbuf[2][4 * 32768];
// tf32 drive [t][mt][half*2048 + o_u*128 + b*4 + c]
__device__ __align__(16) uint32_t g_ubuf[(size_t)HH * 4 * 4096];

__device__ __forceinline__ void grid_barrier(unsigned epoch, int bid, int tid)
{
    __syncthreads();
    if (tid == 0) {
        __threadfence();
        *((volatile unsigned*)&g_arrive[bid]) = epoch;
    }
    if (bid == 0) {
        if (tid < NCTA) {
            while ((int)(*((volatile unsigned*)&g_arrive[tid]) - epoch) < 0) { }
        }
        __syncthreads();
        if (tid == 0) {
            __threadfence();
            *((volatile unsigned*)&g_release) = epoch;
        }
    } else if (tid == 0) {
        while ((int)(*((volatile unsigned*)&g_release) - epoch) < 0) { }
    }
    __syncthreads();
    __threadfence();
}

// 32-CTA group flag barrier: 1 global round trip on the critical path.
__device__ __forceinline__ void group_barrier(unsigned epoch, int mt_, int nt_, int tid)
{
    __threadfence();
    __syncthreads();
    if (tid == 0) {
        *((volatile unsigned*)&g_flag[mt_][nt_]) = epoch;
    }
    if (tid < 32) {
        while ((int)(*((volatile unsigned*)&g_flag[mt_][tid]) - epoch) < 0) { }
    }
    __syncthreads();
}

__device__ __forceinline__ uint32_t f2tf32(float v)
{
    uint32_t r;
    asm("cvt.rna.tf32.f32 %0, %1;" : "=r"(r) : "f"(v));
    return r;
}

__device__ __forceinline__ void mma_tf32(float* d,
                                         uint32_t a0, uint32_t a1, uint32_t a2, uint32_t a3,
                                         uint32_t b0, uint32_t b1)
{
    asm volatile("mma.sync.aligned.m16n8k8.row.col.f32.tf32.tf32.f32 "
                 "{%0,%1,%2,%3}, {%4,%5,%6,%7}, {%8,%9}, {%0,%1,%2,%3};"
                 : "+f"(d[0]), "+f"(d[1]), "+f"(d[2]), "+f"(d[3])
                 : "r"(a0), "r"(a1), "r"(a2), "r"(a3), "r"(b0), "r"(b1));
}

__device__ __forceinline__ void bulk_mc(uint32_t dst_smem, const void* src,
                                        uint32_t bytes, uint32_t mbar, uint16_t mask)
{
    asm volatile("cp.async.bulk.shared::cluster.global.mbarrier::complete_tx::bytes"
                 ".multicast::cluster [%0], [%1], %2, [%3], %4;"
                 :: "r"(dst_smem), "l"(src), "r"(bytes), "r"(mbar), "h"(mask)
                 : "memory");
}

__device__ __forceinline__ void mbar_expect(uint32_t mbar, uint32_t bytes)
{
    asm volatile("mbarrier.arrive.expect_tx.shared.b64 _, [%0], %1;"
                 :: "r"(mbar), "r"(bytes) : "memory");
}

__device__ __forceinline__ void mbar_wait(uint32_t mbar, uint32_t parity)
{
    uint32_t done;
    asm volatile("{\n\t.reg .pred p;\n\t"
                 "mbarrier.try_wait.parity.acquire.cta.shared::cta.b64 p, [%1], %2;\n\t"
                 "selp.b32 %0, 1, 0, p;\n\t}"
                 : "=r"(done) : "r"(mbar), "r"(parity) : "memory");
    if (!done) {
        asm volatile("{\n\t.reg .pred P1;\n\t"
                     "W%=:\n\t"
                     "mbarrier.try_wait.parity.acquire.cta.shared::cta.b64 P1, [%0], %1, 0x989680;\n\t"
                     "@P1 bra.uni D%=;\n\t"
                     "bra.uni W%=;\n\t"
                     "D%=:\n\t}"
                     :: "r"(mbar), "r"(parity) : "memory");
    }
}

extern "C" __global__ void __launch_bounds__(NTHREADS, 1) __cluster_dims__(CLUSTER, 1, 1)
ssm_v5_kernel(const float* __restrict__ x0, const float* __restrict__ u,
              const float* __restrict__ A, const float* __restrict__ Bm,
              float* __restrict__ out)
{
    extern __shared__ uint32_t sm[];
    float* red = (float*)(sm + REDO);

    const int tid = threadIdx.x;
    const int bid = blockIdx.x;
    const int mt = bid >> 5;          // cluster ranks share mt (consecutive bids)
    const int nt = bid & 31;
    const int m0 = mt * MT;
    const int n0 = nt * NT;
    const int w = tid >> 5;
    const int lane = tid & 31;
    const int g = lane >> 2;          // 0..7
    const int c = lane & 3;           // 0..3
    const int ss = w & 1;             // s-strip
    const int kg = w >> 1;            // k-group 0..3
    const int gtid = bid * NTHREADS + tid;

    uint32_t rank;
    asm("mov.u32 %0, %%cluster_ctarank;" : "=r"(rank));

    const uint32_t smb = (uint32_t)__cvta_generic_to_shared(sm);
    const uint32_t mbarA = smb + MBAR_W * 4;
    const uint32_t mbarB = mbarA + 8;
    const uint32_t mbarU = mbarA + 16;

    const unsigned base = *((volatile unsigned*)&g_release);

    if (tid == 0) {
        asm volatile("mbarrier.init.shared.b64 [%0], %1;" :: "r"(mbarA), "r"(1) : "memory");
        asm volatile("mbarrier.init.shared.b64 [%0], %1;" :: "r"(mbarB), "r"(1) : "memory");
        asm volatile("mbarrier.init.shared.b64 [%0], %1;" :: "r"(mbarU), "r"(1) : "memory");
    }
    __syncthreads();
    asm volatile("barrier.cluster.arrive.aligned;" ::: "memory");
    asm volatile("barrier.cluster.wait.aligned;" ::: "memory");

    // ---- init: u -> tf32 ubuf [t][mt][half][o_u][b][4] ----
    for (int j = gtid; j < HH * BSZ * (AD / 4); j += NCTA * NTHREADS) {
        int a4 = j & 31;
        int b = (j >> 5) & 127;
        int t = j >> 12;
        float4 v = *(const float4*)(u + ((size_t)b * HH + t) * AD + a4 * 4);
        uint4 o4 = make_uint4(f2tf32(v.x), f2tf32(v.y), f2tf32(v.z), f2tf32(v.w));
        int umt = b >> 5, bl = b & 31;
        size_t widx = ((size_t)t * 4 + umt) * 4096 + (size_t)(a4 & 1) * 2048
                    + (size_t)(a4 >> 1) * 128 + (size_t)bl * 4;
        *(uint4*)(g_ubuf + widx) = o4;
    }
    // ---- init: xbuf[0] = tf32(x0) in chunked layout; out[:,0,:] = x0 ----
    for (int j = gtid; j < BSZ * (SDIM / 4); j += NCTA * NTHREADS) {
        int K4 = j & 255;             // 4-float chunk within s
        int b = j >> 8;
        float4 v = ((const float4*)x0)[j];
        ((float4*)out)[(size_t)b * OUT_T * (SDIM / 4) + K4] = v;
        uint4 o4 = make_uint4(f2tf32(v.x), f2tf32(v.y), f2tf32(v.z), f2tf32(v.w));
        int xmt = b >> 5, bl = b & 31;
        int o = K4 >> 1;
        size_t widx = (size_t)xmt * 32768 + ((o >= 64) ? 16384u : 0u)
                    + (size_t)(K4 & 1) * 8192 + (size_t)(o & 63) * 128 + (size_t)bl * 4;
        *(uint4*)(g_xbuf[0] + widx) = o4;
    }

    // ---- weights into registers (invariant across all 512 steps) ----
    uint32_t a[WOCT][4];
    {
        const int srow = n0 + ss * 16 + g;
#pragma unroll
        for (int i = 0; i < 32; i++) {          // x octets: k = kg*256 + i*8 + {c, c+4}
            int k0 = (kg * 32 + i) * 8 + c;
            a[i][0] = f2tf32(A[(size_t)srow * SDIM + k0]);
            a[i][1] = f2tf32(A[(size_t)(srow + 8) * SDIM + k0]);
            a[i][2] = f2tf32(A[(size_t)srow * SDIM + k0 + 4]);
            a[i][3] = f2tf32(A[(size_t)(srow + 8) * SDIM + k0 + 4]);
        }
#pragma unroll
        for (int jq = 0; jq < 4; jq++) {        // u octets: k_u = kg*32 + jq*8 + {c, c+4}
            int k0 = (kg * 4 + jq) * 8 + c;
            a[32 + jq][0] = f2tf32(Bm[(size_t)srow * AD + k0]);
            a[32 + jq][1] = f2tf32(Bm[(size_t)(srow + 8) * AD + k0]);
            a[32 + jq][2] = f2tf32(Bm[(size_t)srow * AD + k0 + 4]);
            a[32 + jq][3] = f2tf32(Bm[(size_t)(srow + 8) * AD + k0 + 4]);
        }
    }

    grid_barrier(base + 1, bid, tid);   // init fence (global, once)

    for (int t = 0; t < HH; t++) {
        // ---- stage: chunked multicast bulk DMA ----
        if (tid == 0) {
            mbar_expect(mbarA, 65536);
            mbar_expect(mbarB, 65536);
            mbar_expect(mbarU, 16384);
            // rank r copies slice r (32KB contiguous, layout-identical)
            const uint32_t* xsrc = g_xbuf[t & 1] + (size_t)mt * 32768 + (size_t)rank * 8192;
            bulk_mc(smb + rank * 32768u, xsrc, 32768,
                    (rank < 2) ? mbarA : mbarB, 0xF);
            if (rank >= 2) {
                const uint32_t* usrc = g_ubuf + ((size_t)t * 4 + mt) * 4096
                                     + (size_t)(rank - 2) * 2048;
                bulk_mc(smb + UREG * 4u + (rank - 2) * 8192u, usrc, 8192, mbarU, 0xF);
            }
        }

        // ---- MMA: kg0/1 start on chunk A while chunk B is in flight ----
        float d[4][4];
#pragma unroll
        for (int nn = 0; nn < 4; nn++)
#pragma unroll
            for (int q = 0; q < 4; q++) d[nn][q] = 0.0f;

        mbar_wait((kg >= 2) ? mbarB : mbarA, (uint32_t)(t & 1));
        {
            const uint32_t* xs = sm + ((kg >= 2) ? CHB : CHA)
                               + (kg & 1) * 32 * 128 + g * 4 + c;
#pragma unroll
            for (int i = 0; i < 32; i++) {
#pragma unroll
                for (int nn = 0; nn < 4; nn++) {
                    uint32_t blo = xs[i * 128 + nn * 32];
                    uint32_t bhi = xs[i * 128 + nn * 32 + 8192];
                    mma_tf32(d[nn], a[i][0], a[i][1], a[i][2], a[i][3], blo, bhi);
                }
            }
        }
        mbar_wait(mbarU, (uint32_t)(t & 1));
        {
            const uint32_t* us = sm + UREG + kg * 4 * 128 + g * 4 + c;
#pragma unroll
            for (int jq = 0; jq < 4; jq++) {
#pragma unroll
                for (int nn = 0; nn < 4; nn++) {
                    uint32_t blo = us[jq * 128 + nn * 32];
                    uint32_t bhi = us[jq * 128 + nn * 32 + 2048];
                    mma_tf32(d[nn], a[32 + jq][0], a[32 + jq][1],
                             a[32 + jq][2], a[32 + jq][3], blo, bhi);
                }
            }
        }

        // ---- partials to smem ----
        {
            int rb = w * (16 * RED_STRIDE) + g * RED_STRIDE + 2 * c;
#pragma unroll
            for (int nn = 0; nn < 4; nn++) {
                *(float2*)(red + rb + nn * 8) = make_float2(d[nn][0], d[nn][1]);
                *(float2*)(red + rb + 8 * RED_STRIDE + nn * 8) = make_float2(d[nn][2], d[nn][3]);
            }
        }
        __syncthreads();

        // ---- reduce 4 k-partials; write fp32 out + tf32 xbuf ----
        {
            int b = tid >> 3;
            int s4 = (tid & 7) * 4;
            int ssr = s4 >> 4;
            float acc0 = 0.f, acc1 = 0.f, acc2 = 0.f, acc3 = 0.f;
#pragma unroll
            for (int kk = 0; kk < 4; kk++) {
                int wb = (kk * 2 + ssr) * (16 * RED_STRIDE) + b;
                acc0 += red[wb + ((s4 + 0) & 15) * RED_STRIDE];
                acc1 += red[wb + ((s4 + 1) & 15) * RED_STRIDE];
                acc2 += red[wb + ((s4 + 2) & 15) * RED_STRIDE];
                acc3 += red[wb + ((s4 + 3) & 15) * RED_STRIDE];
            }
            float* op = out + ((size_t)(m0 + b) * OUT_T + (t + 1)) * SDIM + n0 + s4;
            *(float4*)op = make_float4(acc0, acc1, acc2, acc3);

            int K4 = (n0 + s4) >> 2;
            int o = K4 >> 1;
            size_t widx = (size_t)mt * 32768 + ((o >= 64) ? 16384u : 0u)
                        + (size_t)(K4 & 1) * 8192 + (size_t)(o & 63) * 128 + (size_t)b * 4;
            uint32_t* xp = g_xbuf[(t + 1) & 1] + widx;
            uint32_t t0 = f2tf32(acc0), t1 = f2tf32(acc1), t2 = f2tf32(acc2), t3 = f2tf32(acc3);
            asm volatile("st.global.cg.v4.b32 [%0], {%1,%2,%3,%4};"
                         :: "l"(xp), "r"(t0), "r"(t1), "r"(t2), "r"(t3) : "memory");
        }

        // ---- 32-CTA group flag barrier (1 global RT) ----
        group_barrier(base + 2 + t, mt, nt, tid);
    }

    // Bump the epoch stream past all flag epochs so next replay's waits can't
    // be satisfied by stale flags.
    if (bid == 0 && tid == 0) {
        __threadfence();
        *((volatile unsigned*)&g_release) = base + 2 + HH;
    }
}

extern "C" void kernel_launch(void* const* d_in, const int* in_sizes, int n_in,
                              void* d_out, int out_size)
{
    const float* x0 = (const float*)d_in[0];
    const float* u  = (const float*)d_in[1];
    const float* A  = (const float*)d_in[2];
    const float* Bm = (const float*)d_in[3];
    float* out = (float*)d_out;

    cudaFuncSetAttribute(ssm_v5_kernel,
                         cudaFuncAttributeMaxDynamicSharedMemorySize, SMEM_BYTES);

    ssm_v5_kernel<<<NCTA, NTHREADS, SMEM_BYTES>>>(x0, u, A, Bm, out);
}

// round 7
// speedup vs baseline: 1.8240x; 1.8240x over previous
#include <cuda_runtime.h>
#include <cstdint>

// Problem constants
#define BSZ 128
#define SDIM 1024
#define AD 128
#define HH 512
#define OUT_T 513

// Grid/tiling
#define NCTA 128
#define NTHREADS 256
#define CLUSTER 4
#define MT 32
#define NT 32
#define WOCT 36               // per-warp octets: 32 x + 4 u

// SMEM word offsets.
// Chunk A (k 0..511):   words [0, 16384)      = half0 8192 | half1 8192
// Chunk B (k 512..1023):words [16384, 32768)
// U region (k 1024..):  words [32768, 36864)  = half0 2048 | half1 2048
#define CHA 0
#define CHB 16384
#define UREG 32768
#define REDO 36864
#define RED_STRIDE 40
#define RED_W (8 * 16 * RED_STRIDE)   // 5120 words
#define MBAR_W (REDO + RED_W)         // 41984 (byte offset 167936, 8B aligned)
#define SMEM_BYTES ((MBAR_W + 8) * 4)

// Global sync state (zero-init once; epochs monotonic across graph replays)
__device__ unsigned g_arrive[NCTA];
__device__ unsigned g_release;
// One flag per 128-B line: g_flag[mt][nt][0] used, rest is padding.
// (R6 packed all 32 group flags into one line -> false sharing, +1.5us/step.)
__device__ __align__(128) unsigned g_flag[4][32][32];

// tf32 state double buffer; per-mt block of 32768 words laid out EXACTLY like
// smem chunks A|B so staging is 4 contiguous 32KB bulk copies.
__device__ __align__(16) uint32_t g_xbuf[2][4 * 32768];
// tf32 drive [t][mt][half*2048 + o_u*128 + b*4 + c]
__device__ __align__(16) uint32_t g_ubuf[(size_t)HH * 4 * 4096];

__device__ __forceinline__ void grid_barrier(unsigned epoch, int bid, int tid)
{
    __syncthreads();
    if (tid == 0) {
        __threadfence();
        *((volatile unsigned*)&g_arrive[bid]) = epoch;
    }
    if (bid == 0) {
        if (tid < NCTA) {
            while ((int)(*((volatile unsigned*)&g_arrive[tid]) - epoch) < 0) { }
        }
        __syncthreads();
        if (tid == 0) {
            __threadfence();
            *((volatile unsigned*)&g_release) = epoch;
        }
    } else if (tid == 0) {
        while ((int)(*((volatile unsigned*)&g_release) - epoch) < 0) { }
    }
    __syncthreads();
    __threadfence();
}

// 32-CTA group flag barrier: 1 global round trip, padded flags (no false sharing).
__device__ __forceinline__ void group_barrier(unsigned epoch, int mt_, int nt_, int tid)
{
    __threadfence();
    __syncthreads();
    if (tid == 0) {
        *((volatile unsigned*)&g_flag[mt_][nt_][0]) = epoch;
    }
    if (tid < 32) {
        while ((int)(*((volatile unsigned*)&g_flag[mt_][tid][0]) - epoch) < 0) { }
    }
    __syncthreads();
}

__device__ __forceinline__ uint32_t f2tf32(float v)
{
    uint32_t r;
    asm("cvt.rna.tf32.f32 %0, %1;" : "=r"(r) : "f"(v));
    return r;
}

__device__ __forceinline__ void mma_tf32(float* d,
                                         uint32_t a0, uint32_t a1, uint32_t a2, uint32_t a3,
                                         uint32_t b0, uint32_t b1)
{
    asm volatile("mma.sync.aligned.m16n8k8.row.col.f32.tf32.tf32.f32 "
                 "{%0,%1,%2,%3}, {%4,%5,%6,%7}, {%8,%9}, {%0,%1,%2,%3};"
                 : "+f"(d[0]), "+f"(d[1]), "+f"(d[2]), "+f"(d[3])
                 : "r"(a0), "r"(a1), "r"(a2), "r"(a3), "r"(b0), "r"(b1));
}

__device__ __forceinline__ void bulk_mc(uint32_t dst_smem, const void* src,
                                        uint32_t bytes, uint32_t mbar, uint16_t mask)
{
    asm volatile("cp.async.bulk.shared::cluster.global.mbarrier::complete_tx::bytes"
                 ".multicast::cluster [%0], [%1], %2, [%3], %4;"
                 :: "r"(dst_smem), "l"(src), "r"(bytes), "r"(mbar), "h"(mask)
                 : "memory");
}

__device__ __forceinline__ void mbar_expect(uint32_t mbar, uint32_t bytes)
{
    asm volatile("mbarrier.arrive.expect_tx.shared.b64 _, [%0], %1;"
                 :: "r"(mbar), "r"(bytes) : "memory");
}

__device__ __forceinline__ void mbar_wait(uint32_t mbar, uint32_t parity)
{
    uint32_t done;
    asm volatile("{\n\t.reg .pred p;\n\t"
                 "mbarrier.try_wait.parity.acquire.cta.shared::cta.b64 p, [%1], %2;\n\t"
                 "selp.b32 %0, 1, 0, p;\n\t}"
                 : "=r"(done) : "r"(mbar), "r"(parity) : "memory");
    if (!done) {
        asm volatile("{\n\t.reg .pred P1;\n\t"
                     "W%=:\n\t"
                     "mbarrier.try_wait.parity.acquire.cta.shared::cta.b64 P1, [%0], %1, 0x989680;\n\t"
                     "@P1 bra.uni D%=;\n\t"
                     "bra.uni W%=;\n\t"
                     "D%=:\n\t}"
                     :: "r"(mbar), "r"(parity) : "memory");
    }
}

extern "C" __global__ void __launch_bounds__(NTHREADS, 1) __cluster_dims__(CLUSTER, 1, 1)
ssm_v6_kernel(const float* __restrict__ x0, const float* __restrict__ u,
              const float* __restrict__ A, const float* __restrict__ Bm,
              float* __restrict__ out)
{
    extern __shared__ uint32_t sm[];
    float* red = (float*)(sm + REDO);

    const int tid = threadIdx.x;
    const int bid = blockIdx.x;
    const int mt = bid >> 5;          // cluster ranks share mt (consecutive bids)
    const int nt = bid & 31;
    const int m0 = mt * MT;
    const int n0 = nt * NT;
    const int w = tid >> 5;
    const int lane = tid & 31;
    const int g = lane >> 2;          // 0..7
    const int c = lane & 3;           // 0..3
    const int ss = w & 1;             // s-strip
    const int kg = w >> 1;            // k-group 0..3
    const int gtid = bid * NTHREADS + tid;

    uint32_t rank;
    asm("mov.u32 %0, %%cluster_ctarank;" : "=r"(rank));

    const uint32_t smb = (uint32_t)__cvta_generic_to_shared(sm);
    const uint32_t mbarA = smb + MBAR_W * 4;
    const uint32_t mbarB = mbarA + 8;
    const uint32_t mbarU = mbarA + 16;

    const unsigned base = *((volatile unsigned*)&g_release);

    if (tid == 0) {
        asm volatile("mbarrier.init.shared.b64 [%0], %1;" :: "r"(mbarA), "r"(1) : "memory");
        asm volatile("mbarrier.init.shared.b64 [%0], %1;" :: "r"(mbarB), "r"(1) : "memory");
        asm volatile("mbarrier.init.shared.b64 [%0], %1;" :: "r"(mbarU), "r"(1) : "memory");
    }
    __syncthreads();
    asm volatile("barrier.cluster.arrive.aligned;" ::: "memory");
    asm volatile("barrier.cluster.wait.aligned;" ::: "memory");

    // ---- init: u -> tf32 ubuf [t][mt][half][o_u][b][4] ----
    for (int j = gtid; j < HH * BSZ * (AD / 4); j += NCTA * NTHREADS) {
        int a4 = j & 31;
        int b = (j >> 5) & 127;
        int t = j >> 12;
        float4 v = *(const float4*)(u + ((size_t)b * HH + t) * AD + a4 * 4);
        uint4 o4 = make_uint4(f2tf32(v.x), f2tf32(v.y), f2tf32(v.z), f2tf32(v.w));
        int umt = b >> 5, bl = b & 31;
        size_t widx = ((size_t)t * 4 + umt) * 4096 + (size_t)(a4 & 1) * 2048
                    + (size_t)(a4 >> 1) * 128 + (size_t)bl * 4;
        *(uint4*)(g_ubuf + widx) = o4;
    }
    // ---- init: xbuf[0] = tf32(x0) in chunked layout; out[:,0,:] = x0 ----
    for (int j = gtid; j < BSZ * (SDIM / 4); j += NCTA * NTHREADS) {
        int K4 = j & 255;             // 4-float chunk within s
        int b = j >> 8;
        float4 v = ((const float4*)x0)[j];
        ((float4*)out)[(size_t)b * OUT_T * (SDIM / 4) + K4] = v;
        uint4 o4 = make_uint4(f2tf32(v.x), f2tf32(v.y), f2tf32(v.z), f2tf32(v.w));
        int xmt = b >> 5, bl = b & 31;
        int o = K4 >> 1;
        size_t widx = (size_t)xmt * 32768 + ((o >= 64) ? 16384u : 0u)
                    + (size_t)(K4 & 1) * 8192 + (size_t)(o & 63) * 128 + (size_t)bl * 4;
        *(uint4*)(g_xbuf[0] + widx) = o4;
    }

    // ---- weights into registers (invariant across all 512 steps) ----
    uint32_t a[WOCT][4];
    {
        const int srow = n0 + ss * 16 + g;
#pragma unroll
        for (int i = 0; i < 32; i++) {          // x octets: k = kg*256 + i*8 + {c, c+4}
            int k0 = (kg * 32 + i) * 8 + c;
            a[i][0] = f2tf32(A[(size_t)srow * SDIM + k0]);
            a[i][1] = f2tf32(A[(size_t)(srow + 8) * SDIM + k0]);
            a[i][2] = f2tf32(A[(size_t)srow * SDIM + k0 + 4]);
            a[i][3] = f2tf32(A[(size_t)(srow + 8) * SDIM + k0 + 4]);
        }
#pragma unroll
        for (int jq = 0; jq < 4; jq++) {        // u octets: k_u = kg*32 + jq*8 + {c, c+4}
            int k0 = (kg * 4 + jq) * 8 + c;
            a[32 + jq][0] = f2tf32(Bm[(size_t)srow * AD + k0]);
            a[32 + jq][1] = f2tf32(Bm[(size_t)(srow + 8) * AD + k0]);
            a[32 + jq][2] = f2tf32(Bm[(size_t)srow * AD + k0 + 4]);
            a[32 + jq][3] = f2tf32(Bm[(size_t)(srow + 8) * AD + k0 + 4]);
        }
    }

    grid_barrier(base + 1, bid, tid);   // init fence (global, once)

    for (int t = 0; t < HH; t++) {
        // ---- stage: chunked multicast bulk DMA ----
        if (tid == 0) {
            mbar_expect(mbarA, 65536);
            mbar_expect(mbarB, 65536);
            mbar_expect(mbarU, 16384);
            // rank r copies slice r (32KB contiguous, layout-identical)
            const uint32_t* xsrc = g_xbuf[t & 1] + (size_t)mt * 32768 + (size_t)rank * 8192;
            bulk_mc(smb + rank * 32768u, xsrc, 32768,
                    (rank < 2) ? mbarA : mbarB, 0xF);
            if (rank >= 2) {
                const uint32_t* usrc = g_ubuf + ((size_t)t * 4 + mt) * 4096
                                     + (size_t)(rank - 2) * 2048;
                bulk_mc(smb + UREG * 4u + (rank - 2) * 8192u, usrc, 8192, mbarU, 0xF);
            }
        }

        // ---- MMA: kg0/1 start on chunk A while chunk B is in flight ----
        float d[4][4];
#pragma unroll
        for (int nn = 0; nn < 4; nn++)
#pragma unroll
            for (int q = 0; q < 4; q++) d[nn][q] = 0.0f;

        mbar_wait((kg >= 2) ? mbarB : mbarA, (uint32_t)(t & 1));
        {
            const uint32_t* xs = sm + ((kg >= 2) ? CHB : CHA)
                               + (kg & 1) * 32 * 128 + g * 4 + c;
#pragma unroll
            for (int i = 0; i < 32; i++) {
#pragma unroll
                for (int nn = 0; nn < 4; nn++) {
                    uint32_t blo = xs[i * 128 + nn * 32];
                    uint32_t bhi = xs[i * 128 + nn * 32 + 8192];
                    mma_tf32(d[nn], a[i][0], a[i][1], a[i][2], a[i][3], blo, bhi);
                }
            }
        }
        mbar_wait(mbarU, (uint32_t)(t & 1));
        {
            const uint32_t* us = sm + UREG + kg * 4 * 128 + g * 4 + c;
#pragma unroll
            for (int jq = 0; jq < 4; jq++) {
#pragma unroll
                for (int nn = 0; nn < 4; nn++) {
                    uint32_t blo = us[jq * 128 + nn * 32];
                    uint32_t bhi = us[jq * 128 + nn * 32 + 2048];
                    mma_tf32(d[nn], a[32 + jq][0], a[32 + jq][1],
                             a[32 + jq][2], a[32 + jq][3], blo, bhi);
                }
            }
        }

        // ---- partials to smem ----
        {
            int rb = w * (16 * RED_STRIDE) + g * RED_STRIDE + 2 * c;
#pragma unroll
            for (int nn = 0; nn < 4; nn++) {
                *(float2*)(red + rb + nn * 8) = make_float2(d[nn][0], d[nn][1]);
                *(float2*)(red + rb + 8 * RED_STRIDE + nn * 8) = make_float2(d[nn][2], d[nn][3]);
            }
        }
        __syncthreads();

        // ---- reduce 4 k-partials; write fp32 out + tf32 xbuf ----
        {
            int b = tid >> 3;
            int s4 = (tid & 7) * 4;
            int ssr = s4 >> 4;
            float acc0 = 0.f, acc1 = 0.f, acc2 = 0.f, acc3 = 0.f;
#pragma unroll
            for (int kk = 0; kk < 4; kk++) {
                int wb = (kk * 2 + ssr) * (16 * RED_STRIDE) + b;
                acc0 += red[wb + ((s4 + 0) & 15) * RED_STRIDE];
                acc1 += red[wb + ((s4 + 1) & 15) * RED_STRIDE];
                acc2 += red[wb + ((s4 + 2) & 15) * RED_STRIDE];
                acc3 += red[wb + ((s4 + 3) & 15) * RED_STRIDE];
            }
            float* op = out + ((size_t)(m0 + b) * OUT_T + (t + 1)) * SDIM + n0 + s4;
            *(float4*)op = make_float4(acc0, acc1, acc2, acc3);

            int K4 = (n0 + s4) >> 2;
            int o = K4 >> 1;
            size_t widx = (size_t)mt * 32768 + ((o >= 64) ? 16384u : 0u)
                        + (size_t)(K4 & 1) * 8192 + (size_t)(o & 63) * 128 + (size_t)b * 4;
            uint32_t* xp = g_xbuf[(t + 1) & 1] + widx;
            uint32_t t0 = f2tf32(acc0), t1 = f2tf32(acc1), t2 = f2tf32(acc2), t3 = f2tf32(acc3);
            asm volatile("st.global.cg.v4.b32 [%0], {%1,%2,%3,%4};"
                         :: "l"(xp), "r"(t0), "r"(t1), "r"(t2), "r"(t3) : "memory");
        }

        // ---- 32-CTA group flag barrier (1 global RT, padded flags) ----
        group_barrier(base + 2 + t, mt, nt, tid);
    }

    // Bump the epoch stream past all flag epochs so next replay's waits can't
    // be satisfied by stale flags.
    if (bid == 0 && tid == 0) {
        __threadfence();
        *((volatile unsigned*)&g_release) = base + 2 + HH;
    }
}

extern "C" void kernel_launch(void* const* d_in, const int* in_sizes, int n_in,
                              void* d_out, int out_size)
{
    const float* x0 = (const float*)d_in[0];
    const float* u  = (const float*)d_in[1];
    const float* A  = (const float*)d_in[2];
    const float* Bm = (const float*)d_in[3];
    float* out = (float*)d_out;

    cudaFuncSetAttribute(ssm_v6_kernel,
                         cudaFuncAttributeMaxDynamicSharedMemorySize, SMEM_BYTES);

    ssm_v6_kernel<<<NCTA, NTHREADS, SMEM_BYTES>>>(x0, u, A, Bm, out);
}